// round 2
// baseline (speedup 1.0000x reference)
#include <cuda_runtime.h>

#define DIN  128
#define DOUT 128
#define KK   256      // combined K = DIN (agg) + DIN (x)
#define NB   48       // nodes per GEMM block
#define MAXN 50000

#define SMEM_BYTES (KK*DOUT*4 + NB*KK*8)   // 131072 + 98304 = 229376 (< 227KB cap)

// Scratch (no allocation allowed): aggregation buffer + pre-transposed weights.
__device__ float g_agg[MAXN * DIN];
__device__ float g_Wp[KK * DOUT];          // g_Wp[k*128 + o] = Wc[o][k]
__device__ int   g_is64;                   // edge_index dtype flag

// ---------------------------------------------------------------- zero agg
__global__ void zero_agg_kernel(int n4) {
    int i = blockIdx.x * blockDim.x + threadIdx.x;
    if (i == 0) g_is64 = 1;
    if (i < n4) ((float4*)g_agg)[i] = make_float4(0.f, 0.f, 0.f, 0.f);
}

// ---------------------------------------------------------------- dtype probe
// If the buffer really is int64 indices in [0,N), every 64-bit word is < N.
// If it's int32 data read as int64, the high word is a random index (almost
// surely nonzero somewhere in 1024 samples) -> value >= N -> int32 detected.
__global__ void detect_kernel(const long long* __restrict__ ei, int nwords, int N) {
    int i = threadIdx.x + blockIdx.x * blockDim.x;
    if (i < nwords) {
        unsigned long long v = (unsigned long long)ei[i];
        if (v >= (unsigned long long)N) atomicAnd(&g_is64, 0);
    }
}

// ---------------------------------------------------------------- W prep
__global__ void wprep_kernel(const float* __restrict__ W_rel,
                             const float* __restrict__ W_root) {
    int idx = blockIdx.x * blockDim.x + threadIdx.x;   // idx = k*128 + o
    if (idx >= KK * DOUT) return;
    int o = idx & (DOUT - 1);
    int k = idx >> 7;
    float v = (k < DIN) ? W_rel[o * DIN + k] : W_root[o * DIN + (k - DIN)];
    g_Wp[idx] = v;
}

// ---------------------------------------------------------------- aggregation
// One warp per edge: 512B coalesced gather of x[src], vector red to agg[dst].
__global__ void aggregate_kernel(const float4* __restrict__ x,
                                 const void* __restrict__ ei_raw, int E, int N) {
    int gtid = blockIdx.x * blockDim.x + threadIdx.x;
    int e = gtid >> 5;
    int lane = gtid & 31;
    if (e >= E) return;

    long long s, d;
    if (g_is64) {
        const long long* ei = (const long long*)ei_raw;
        s = __ldg(&ei[e]);
        d = __ldg(&ei[E + e]);
    } else {
        const int* ei = (const int*)ei_raw;
        s = __ldg(&ei[e]);
        d = __ldg(&ei[E + e]);
    }
    if ((unsigned long long)s >= (unsigned long long)N ||
        (unsigned long long)d >= (unsigned long long)N) return;  // never IMA

    float4 v = x[s * 32 + lane];
    float* dst = g_agg + (size_t)d * DIN + (lane << 2);
    asm volatile("red.global.add.v4.f32 [%0], {%1, %2, %3, %4};"
                 :: "l"(dst), "f"(v.x), "f"(v.y), "f"(v.z), "f"(v.w)
                 : "memory");
}

// ---------------------------------------------------------------- GEMM (f32x2)
__device__ __forceinline__ unsigned long long fma2(unsigned long long a,
                                                   unsigned long long b,
                                                   unsigned long long c) {
    unsigned long long d;
    asm("fma.rn.f32x2 %0, %1, %2, %3;" : "=l"(d) : "l"(a), "l"(b), "l"(c));
    return d;
}

// out[i][o] = relu( sum_k [agg|x][i][k] * Wc[o][k] + b[o] )
// Block: 48 nodes x 128 outputs. Thread: 6 nodes x 4 outputs (12 f32x2 accs).
__global__ __launch_bounds__(256, 1)
void gemm_kernel(const float* __restrict__ x, const float* __restrict__ bias,
                 float* __restrict__ out, int N) {
    extern __shared__ float smem[];
    float* sW = smem;                                       // [KK*DOUT] k-major
    float2* sIn = (float2*)(smem + KK * DOUT);              // [NB*KK] (v,v) pairs
    unsigned long long* sInP = (unsigned long long*)sIn;

    int tid = threadIdx.x;
    int node0 = blockIdx.x * NB;

    // W: straight coalesced copy (already k-major)
    {
        const float4* Wg4 = (const float4*)g_Wp;
        float4* sW4 = (float4*)sW;
        #pragma unroll
        for (int i = 0; i < (KK * DOUT / 4) / 256; i++)
            sW4[tid + i * 256] = Wg4[tid + i * 256];
    }

    // Inputs: concat(agg_row, x_row), duplicated (v,v) for f32x2 broadcast
    for (int i = tid; i < NB * KK; i += 256) {
        int n = i >> 8;            // i / KK
        int k = i & (KK - 1);
        int node = node0 + n;
        float v = 0.f;
        if (node < N)
            v = (k < DIN) ? g_agg[node * DIN + k] : x[node * DIN + (k - DIN)];
        sIn[n * KK + k] = make_float2(v, v);
    }
    __syncthreads();

    int pg = tid & 31;       // outputs 4pg..4pg+3
    int ng = tid >> 5;
    int nb = ng * 6;

    unsigned long long acc[12];
    #pragma unroll
    for (int i = 0; i < 12; i++) acc[i] = 0ull;

    #pragma unroll 2
    for (int k = 0; k < KK; k += 2) {
        ulonglong2 wa = *(const ulonglong2*)(sW + k * DOUT + 4 * pg);
        ulonglong2 wb = *(const ulonglong2*)(sW + (k + 1) * DOUT + 4 * pg);
        #pragma unroll
        for (int i = 0; i < 6; i++) {
            ulonglong2 a = *(const ulonglong2*)(sInP + ((nb + i) * KK + k));
            acc[2*i]   = fma2(a.x, wa.x, acc[2*i]);
            acc[2*i+1] = fma2(a.x, wa.y, acc[2*i+1]);
            acc[2*i]   = fma2(a.y, wb.x, acc[2*i]);
            acc[2*i+1] = fma2(a.y, wb.y, acc[2*i+1]);
        }
    }

    float4 bb = ((const float4*)bias)[pg];
    #pragma unroll
    for (int i = 0; i < 6; i++) {
        int node = node0 + nb + i;
        if (node < N) {
            float p0x, p0y, p1x, p1y;
            asm("mov.b64 {%0, %1}, %2;" : "=f"(p0x), "=f"(p0y) : "l"(acc[2*i]));
            asm("mov.b64 {%0, %1}, %2;" : "=f"(p1x), "=f"(p1y) : "l"(acc[2*i+1]));
            float4 r;
            r.x = fmaxf(p0x + bb.x, 0.f);
            r.y = fmaxf(p0y + bb.y, 0.f);
            r.z = fmaxf(p1x + bb.z, 0.f);
            r.w = fmaxf(p1y + bb.w, 0.f);
            ((float4*)(out + (size_t)node * DOUT))[pg] = r;
        }
    }
}

// ---------------------------------------------------------------- launch
extern "C" void kernel_launch(void* const* d_in, const int* in_sizes, int n_in,
                              void* d_out, int out_size) {
    const float* x      = (const float*)d_in[0];
    const void*  ei     = d_in[1];
    const float* W_rel  = (const float*)d_in[2];
    const float* b_rel  = (const float*)d_in[3];
    const float* W_root = (const float*)d_in[4];
    float* out = (float*)d_out;

    int N = in_sizes[0] / DIN;     // 50000
    int E = in_sizes[1] / 2;       // 800000

    int n4 = (N * DIN) / 4;
    zero_agg_kernel<<<(n4 + 255) / 256, 256>>>(n4);

    int probe = 1024;              // 1024 int64 words = 2048 int32 words, in bounds
    detect_kernel<<<(probe + 255) / 256, 256>>>((const long long*)ei, probe, N);

    wprep_kernel<<<(KK * DOUT + 255) / 256, 256>>>(W_rel, W_root);

    long long total_threads = (long long)E * 32;
    int agg_blocks = (int)((total_threads + 255) / 256);
    aggregate_kernel<<<agg_blocks, 256>>>((const float4*)x, ei, E, N);

    cudaFuncSetAttribute(gemm_kernel,
                         cudaFuncAttributeMaxDynamicSharedMemorySize, SMEM_BYTES);
    gemm_kernel<<<(N + NB - 1) / NB, 256, SMEM_BYTES>>>(x, b_rel, out, N);
}

// round 5
// speedup vs baseline: 1.9928x; 1.9928x over previous
#include <cuda_runtime.h>
#include <cuda_bf16.h>
#include <cstdint>

#define DIN   128
#define DOUT  128
#define MTILE 128
#define KC    64            // K elems per chunk
#define NCHUNK 4
#define MAXN  50000
#define PITCH 72            // bf16 per smem row (64 + 8 pad) -> conflict-free ldmatrix

// smem: 4 tiles [128][PITCH] bf16: Ah, Al, Bh, Bl
#define T_ELEMS (128 * PITCH)
#define SMEM_TOTAL (4 * T_ELEMS * 2)   // 73728 bytes

__device__ float g_agg[MAXN * DIN];
__device__ int   g_is64;

// ---------------------------------------------------------------- helpers
__device__ __forceinline__ uint32_t smem_u32(const void* p) {
    uint32_t a;
    asm("{ .reg .u64 t; cvta.to.shared.u64 t, %1; cvt.u32.u64 %0, t; }" : "=r"(a) : "l"(p));
    return a;
}
#define LDMX4(r0, r1, r2, r3, a) \
    asm volatile("ldmatrix.sync.aligned.m8n8.x4.shared.b16 {%0,%1,%2,%3}, [%4];" \
                 : "=r"(r0), "=r"(r1), "=r"(r2), "=r"(r3) : "r"(a))
#define MMA(c, a0, a1, a2, a3, b0, b1) \
    asm volatile("mma.sync.aligned.m16n8k16.row.col.f32.bf16.bf16.f32 " \
                 "{%0,%1,%2,%3}, {%4,%5,%6,%7}, {%8,%9}, {%0,%1,%2,%3};" \
                 : "+f"((c)[0]), "+f"((c)[1]), "+f"((c)[2]), "+f"((c)[3]) \
                 : "r"(a0), "r"(a1), "r"(a2), "r"(a3), "r"(b0), "r"(b1))

__device__ __forceinline__ void split4(float4 v, uint2& hi, uint2& lo) {
    __nv_bfloat16 hx = __float2bfloat16(v.x), hy = __float2bfloat16(v.y);
    __nv_bfloat16 hz = __float2bfloat16(v.z), hw = __float2bfloat16(v.w);
    __nv_bfloat16 lx = __float2bfloat16(v.x - __bfloat162float(hx));
    __nv_bfloat16 ly = __float2bfloat16(v.y - __bfloat162float(hy));
    __nv_bfloat16 lz = __float2bfloat16(v.z - __bfloat162float(hz));
    __nv_bfloat16 lw = __float2bfloat16(v.w - __bfloat162float(hw));
    hi.x = ((uint32_t)__bfloat16_as_ushort(hy) << 16) | __bfloat16_as_ushort(hx);
    hi.y = ((uint32_t)__bfloat16_as_ushort(hw) << 16) | __bfloat16_as_ushort(hz);
    lo.x = ((uint32_t)__bfloat16_as_ushort(ly) << 16) | __bfloat16_as_ushort(lx);
    lo.y = ((uint32_t)__bfloat16_as_ushort(lw) << 16) | __bfloat16_as_ushort(lz);
}

// ---------------------------------------------------------------- small kernels
__global__ void zero_agg_kernel(int n4) {
    int i = blockIdx.x * blockDim.x + threadIdx.x;
    if (i == 0) g_is64 = 1;
    if (i < n4) ((float4*)g_agg)[i] = make_float4(0.f, 0.f, 0.f, 0.f);
}
__global__ void detect_kernel(const long long* __restrict__ ei, int nwords, int N) {
    int i = threadIdx.x + blockIdx.x * blockDim.x;
    if (i < nwords && (unsigned long long)ei[i] >= (unsigned long long)N)
        atomicAnd(&g_is64, 0);
}
__global__ void aggregate_kernel(const float4* __restrict__ x,
                                 const void* __restrict__ ei_raw, int E, int N) {
    int gtid = blockIdx.x * blockDim.x + threadIdx.x;
    int e = gtid >> 5, lane = gtid & 31;
    if (e >= E) return;
    long long s, d;
    if (g_is64) {
        const long long* ei = (const long long*)ei_raw;
        s = __ldg(&ei[e]); d = __ldg(&ei[E + e]);
    } else {
        const int* ei = (const int*)ei_raw;
        s = __ldg(&ei[e]); d = __ldg(&ei[E + e]);
    }
    if ((unsigned long long)s >= (unsigned long long)N ||
        (unsigned long long)d >= (unsigned long long)N) return;
    float4 v = x[s * 32 + lane];
    float* dst = g_agg + (size_t)d * DIN + (lane << 2);
    asm volatile("red.global.add.v4.f32 [%0], {%1, %2, %3, %4};"
                 :: "l"(dst), "f"(v.x), "f"(v.y), "f"(v.z), "f"(v.w) : "memory");
}

// ---------------------------------------------------------------- HMMA GEMM
// out[i][o] = relu( [agg|x][i][:] . [W_rel|W_root][o][:] + b[o] )
__global__ __launch_bounds__(256, 1)
void gemm_hmma_kernel(const float* __restrict__ x,
                      const float* __restrict__ W_rel,
                      const float* __restrict__ W_root,
                      const float* __restrict__ bias,
                      float* __restrict__ out, int N) {
    extern __shared__ __nv_bfloat16 smem[];
    __nv_bfloat16* sAh = smem;
    __nv_bfloat16* sAl = smem + T_ELEMS;
    __nv_bfloat16* sBh = smem + 2 * T_ELEMS;
    __nv_bfloat16* sBl = smem + 3 * T_ELEMS;

    int tid = threadIdx.x, wid = tid >> 5, lane = tid & 31;
    int wm = wid & 3, wn = wid >> 2;        // warp tile: m32 (wm) x n64 (wn)
    int node0 = blockIdx.x * MTILE;

    float acc[2][8][4];
    #pragma unroll
    for (int a = 0; a < 2; a++)
        #pragma unroll
        for (int b = 0; b < 8; b++)
            #pragma unroll
            for (int c = 0; c < 4; c++) acc[a][b][c] = 0.f;

    // ldmatrix smem byte addresses (chunk-local k handled by +kt*32B)
    uint32_t base = smem_u32(smem);
    // A: lanes%16 -> row within m16 tile, lane/16 -> k-half (8 elems)
    uint32_t aoff = (uint32_t)((wm * 32 + (lane & 15)) * PITCH + (lane >> 4) * 8) * 2;
    // B: row n, k-half from bit3
    uint32_t brow = (uint32_t)(wn * 64 + (lane & 7) + ((lane >> 4) << 3));
    uint32_t boff = (uint32_t)(brow * PITCH + ((lane >> 3) & 1) * 8) * 2;

    for (int c = 0; c < NCHUNK; c++) {
        // ---- load + split A tile: 128 x 64 f32 -> bf16 hi/lo
        const float* asrc = (c < 2) ? g_agg + (size_t)node0 * DIN + c * KC
                                    : x + (size_t)node0 * DIN + (c - 2) * KC;
        #pragma unroll
        for (int i = 0; i < 8; i++) {
            int idx = tid + i * 256;             // [0,2048)
            int row = idx >> 4, c4 = idx & 15;
            float4 v = make_float4(0.f, 0.f, 0.f, 0.f);
            if (node0 + row < N) v = ((const float4*)(asrc + (size_t)row * DIN))[c4];
            uint2 h, l; split4(v, h, l);
            *(uint2*)((char*)sAh + row * (PITCH * 2) + c4 * 8) = h;
            *(uint2*)((char*)sAl + row * (PITCH * 2) + c4 * 8) = l;
        }
        // ---- load + split B tile: 128 outs x 64 k
        const float* bsrc = (c < 2) ? W_rel + c * KC : W_root + (c - 2) * KC;
        #pragma unroll
        for (int i = 0; i < 8; i++) {
            int idx = tid + i * 256;
            int row = idx >> 4, c4 = idx & 15;
            float4 v = ((const float4*)(bsrc + (size_t)row * DIN))[c4];
            uint2 h, l; split4(v, h, l);
            *(uint2*)((char*)sBh + row * (PITCH * 2) + c4 * 8) = h;
            *(uint2*)((char*)sBl + row * (PITCH * 2) + c4 * 8) = l;
        }
        __syncthreads();

        // ---- 4 k16 steps
        #pragma unroll
        for (int kt = 0; kt < 4; kt++) {
            uint32_t kb = kt * 32;               // 16 bf16 = 32B
            uint32_t Ah[8], Al[8], Bh[16], Bl[16];
            #pragma unroll
            for (int tm = 0; tm < 2; tm++) {
                uint32_t a = base + aoff + (uint32_t)(tm * 16 * PITCH) * 2 + kb;
                LDMX4(Ah[tm*4+0], Ah[tm*4+1], Ah[tm*4+2], Ah[tm*4+3], a);
                LDMX4(Al[tm*4+0], Al[tm*4+1], Al[tm*4+2], Al[tm*4+3],
                      a + (uint32_t)T_ELEMS * 2);
            }
            #pragma unroll
            for (int p = 0; p < 4; p++) {
                uint32_t b = base + (uint32_t)(2 * T_ELEMS) * 2 + boff
                           + (uint32_t)(p * 16 * PITCH) * 2 + kb;
                LDMX4(Bh[p*4+0], Bh[p*4+1], Bh[p*4+2], Bh[p*4+3], b);
                LDMX4(Bl[p*4+0], Bl[p*4+1], Bl[p*4+2], Bl[p*4+3],
                      b + (uint32_t)T_ELEMS * 2);
            }
            #pragma unroll
            for (int tm = 0; tm < 2; tm++)
                #pragma unroll
                for (int tn = 0; tn < 8; tn++) {
                    int bi = (tn >> 1) * 4 + (tn & 1) * 2;
                    MMA(acc[tm][tn], Ah[tm*4+0], Ah[tm*4+1], Ah[tm*4+2], Ah[tm*4+3],
                        Bh[bi], Bh[bi+1]);
                    MMA(acc[tm][tn], Al[tm*4+0], Al[tm*4+1], Al[tm*4+2], Al[tm*4+3],
                        Bh[bi], Bh[bi+1]);
                    MMA(acc[tm][tn], Ah[tm*4+0], Ah[tm*4+1], Ah[tm*4+2], Ah[tm*4+3],
                        Bl[bi], Bl[bi+1]);
                }
        }
        __syncthreads();
    }

    // ---- epilogue: bias + relu, float2 stores from fragments
    #pragma unroll
    for (int tn = 0; tn < 8; tn++) {
        int col = wn * 64 + tn * 8 + 2 * (lane & 3);
        float2 bb = *(const float2*)&bias[col];
        #pragma unroll
        for (int tm = 0; tm < 2; tm++) {
            int row = node0 + wm * 32 + tm * 16 + (lane >> 2);
            if (row < N) {
                float2 v0;
                v0.x = fmaxf(acc[tm][tn][0] + bb.x, 0.f);
                v0.y = fmaxf(acc[tm][tn][1] + bb.y, 0.f);
                *(float2*)(out + (size_t)row * DOUT + col) = v0;
            }
            if (row + 8 < N) {
                float2 v1;
                v1.x = fmaxf(acc[tm][tn][2] + bb.x, 0.f);
                v1.y = fmaxf(acc[tm][tn][3] + bb.y, 0.f);
                *(float2*)(out + (size_t)(row + 8) * DOUT + col) = v1;
            }
        }
    }
}

// ---------------------------------------------------------------- launch
extern "C" void kernel_launch(void* const* d_in, const int* in_sizes, int n_in,
                              void* d_out, int out_size) {
    const float* x      = (const float*)d_in[0];
    const void*  ei     = d_in[1];
    const float* W_rel  = (const float*)d_in[2];
    const float* b_rel  = (const float*)d_in[3];
    const float* W_root = (const float*)d_in[4];
    float* out = (float*)d_out;

    int N = in_sizes[0] / DIN;     // 50000
    int E = in_sizes[1] / 2;       // 800000

    int n4 = (N * DIN) / 4;
    zero_agg_kernel<<<(n4 + 255) / 256, 256>>>(n4);
    detect_kernel<<<4, 256>>>((const long long*)ei, 1024, N);

    long long total_threads = (long long)E * 32;
    aggregate_kernel<<<(int)((total_threads + 255) / 256), 256>>>((const float4*)x, ei, E, N);

    cudaFuncSetAttribute(gemm_hmma_kernel,
                         cudaFuncAttributeMaxDynamicSharedMemorySize, SMEM_TOTAL);
    gemm_hmma_kernel<<<(N + MTILE - 1) / MTILE, 256, SMEM_TOTAL>>>(x, W_rel, W_root, b_rel, out, N);
}